// round 1
// baseline (speedup 1.0000x reference)
#include <cuda_runtime.h>
#include <math.h>

#define B_ROWS 4096
#define D_IN   1024
#define D_H    1024
#define K_DIM  2048   // D_IN + D_H
#define N_DIM  4096   // 4 * D_H

#define BM 128
#define BN 128
#define BK 16

// Scratch for z = combined @ W^T + b   [B_ROWS, N_DIM]  (64 MB, static device alloc)
__device__ float g_z[(size_t)B_ROWS * N_DIM];

// ---------------------------------------------------------------------------
// GEMM: z[m, n] = sum_k A[m,k] * B[n,k] + bias[n]
//   A[m,k] = inputs[m,k]        (k < 1024)
//          = h_prev[m,k-1024]   (k >= 1024)
//   B[n,k] = W_g[n % 1024, k],  g = n / 1024  (gate: i, f, c, o)
// CTA tile 128x128, K-tile 16, 256 threads, 8x8 per-thread micro-tile.
// ---------------------------------------------------------------------------
__global__ __launch_bounds__(256) void lstm_gemm(
    const float* __restrict__ x, const float* __restrict__ hprev,
    const float* __restrict__ W0, const float* __restrict__ W1,
    const float* __restrict__ W2, const float* __restrict__ W3,
    const float* __restrict__ b0, const float* __restrict__ b1,
    const float* __restrict__ b2, const float* __restrict__ b3)
{
    __shared__ float As[BK][BM];
    __shared__ float Bs[BK][BN];

    const int m0 = blockIdx.y * BM;
    const int n0 = blockIdx.x * BN;
    const int gate = n0 >> 10;              // 128 | 1024 -> whole tile in one gate
    const float* __restrict__ Wg = (gate == 0) ? W0 : (gate == 1) ? W1 : (gate == 2) ? W2 : W3;
    const float* __restrict__ bg = (gate == 0) ? b0 : (gate == 1) ? b1 : (gate == 2) ? b2 : b3;
    const int j0 = n0 & 1023;               // row offset within the gate's W

    const int tid = threadIdx.x;
    const int tx = tid & 15;                // 16 threads along N
    const int ty = tid >> 4;                // 16 threads along M

    float acc[8][8];
    #pragma unroll
    for (int i = 0; i < 8; i++)
        #pragma unroll
        for (int j = 0; j < 8; j++)
            acc[i][j] = 0.0f;

    for (int kt = 0; kt < K_DIM; kt += BK) {
        // ---- load A tile (from x or h_prev; BK=16 never straddles the seam) ----
        const float* Asrc;
        int kA;
        if (kt < D_IN) { Asrc = x;     kA = kt; }
        else           { Asrc = hprev; kA = kt - D_IN; }

        #pragma unroll
        for (int l = 0; l < 2; l++) {
            const int f  = l * 256 + tid;   // 512 float4 per tile
            const int r  = f >> 2;          // row within tile [0,128)
            const int kq = f & 3;           // which float4 along K

            float4 va = *reinterpret_cast<const float4*>(
                &Asrc[(size_t)(m0 + r) * D_IN + kA + kq * 4]);
            As[kq * 4 + 0][r] = va.x;
            As[kq * 4 + 1][r] = va.y;
            As[kq * 4 + 2][r] = va.z;
            As[kq * 4 + 3][r] = va.w;

            float4 vb = *reinterpret_cast<const float4*>(
                &Wg[(size_t)(j0 + r) * K_DIM + kt + kq * 4]);
            Bs[kq * 4 + 0][r] = vb.x;
            Bs[kq * 4 + 1][r] = vb.y;
            Bs[kq * 4 + 2][r] = vb.z;
            Bs[kq * 4 + 3][r] = vb.w;
        }
        __syncthreads();

        // ---- outer-product accumulate ----
        #pragma unroll
        for (int k = 0; k < BK; k++) {
            float a[8], b[8];
            *reinterpret_cast<float4*>(&a[0]) = *reinterpret_cast<const float4*>(&As[k][ty * 8]);
            *reinterpret_cast<float4*>(&a[4]) = *reinterpret_cast<const float4*>(&As[k][ty * 8 + 4]);
            *reinterpret_cast<float4*>(&b[0]) = *reinterpret_cast<const float4*>(&Bs[k][tx * 8]);
            *reinterpret_cast<float4*>(&b[4]) = *reinterpret_cast<const float4*>(&Bs[k][tx * 8 + 4]);
            #pragma unroll
            for (int i = 0; i < 8; i++)
                #pragma unroll
                for (int j = 0; j < 8; j++)
                    acc[i][j] = fmaf(a[i], b[j], acc[i][j]);
        }
        __syncthreads();
    }

    // ---- add bias, store z ----
    float bias[8];
    *reinterpret_cast<float4*>(&bias[0]) = *reinterpret_cast<const float4*>(&bg[j0 + tx * 8]);
    *reinterpret_cast<float4*>(&bias[4]) = *reinterpret_cast<const float4*>(&bg[j0 + tx * 8 + 4]);

    #pragma unroll
    for (int i = 0; i < 8; i++) {
        const int m = m0 + ty * 8 + i;
        float* zrow = &g_z[(size_t)m * N_DIM + n0 + tx * 8];
        float4 v0, v1;
        v0.x = acc[i][0] + bias[0];
        v0.y = acc[i][1] + bias[1];
        v0.z = acc[i][2] + bias[2];
        v0.w = acc[i][3] + bias[3];
        v1.x = acc[i][4] + bias[4];
        v1.y = acc[i][5] + bias[5];
        v1.z = acc[i][6] + bias[6];
        v1.w = acc[i][7] + bias[7];
        *reinterpret_cast<float4*>(&zrow[0]) = v0;
        *reinterpret_cast<float4*>(&zrow[4]) = v1;
    }
}

// ---------------------------------------------------------------------------
// Gate epilogue: read z (4 gates), c_prev -> h_next, c_next
// Output layout: out[0 : B*D_H) = h_next, out[B*D_H : 2*B*D_H) = c_next
// ---------------------------------------------------------------------------
__global__ __launch_bounds__(256) void lstm_epilogue(
    const float* __restrict__ cprev, float* __restrict__ out)
{
    const int idx = blockIdx.x * blockDim.x + threadIdx.x;   // [0, B*D_H)
    const int m = idx >> 10;
    const int j = idx & 1023;
    const size_t base = (size_t)m * N_DIM + j;

    const float zi = g_z[base];
    const float zf = g_z[base + 1024];
    const float zc = g_z[base + 2048];
    const float zo = g_z[base + 3072];

    const float ig = 1.0f / (1.0f + expf(-zi));
    const float fg = 1.0f / (1.0f + expf(-zf));
    const float cg = tanhf(zc);
    const float og = 1.0f / (1.0f + expf(-zo));

    const float cn = fg * cprev[idx] + ig * cg;
    const float hn = og * tanhf(cn);

    out[idx] = hn;
    out[(size_t)B_ROWS * D_H + idx] = cn;
}

extern "C" void kernel_launch(void* const* d_in, const int* in_sizes, int n_in,
                              void* d_out, int out_size)
{
    const float* x  = (const float*)d_in[0];   // inputs  [4096,1024]
    const float* h  = (const float*)d_in[1];   // h_prev  [4096,1024]
    const float* c  = (const float*)d_in[2];   // c_prev  [4096,1024]
    const float* Wi = (const float*)d_in[3];   // [1024,2048]
    const float* bi = (const float*)d_in[4];   // [1024]
    const float* Wf = (const float*)d_in[5];
    const float* bf = (const float*)d_in[6];
    const float* Wc = (const float*)d_in[7];
    const float* bc = (const float*)d_in[8];
    const float* Wo = (const float*)d_in[9];
    const float* bo = (const float*)d_in[10];
    float* out = (float*)d_out;

    dim3 grid(N_DIM / BN, B_ROWS / BM);        // 32 x 32 = 1024 CTAs
    lstm_gemm<<<grid, 256>>>(x, h, Wi, Wf, Wc, Wo, bi, bf, bc, bo);

    lstm_epilogue<<<(B_ROWS * D_H) / 256, 256>>>(c, out);
}

// round 3
// speedup vs baseline: 2.9797x; 2.9797x over previous
#include <cuda_runtime.h>
#include <cuda_fp16.h>
#include <math.h>
#include <stdint.h>

#define B_ROWS 4096
#define D_H    1024
#define K_DIM  2048
#define N_DIM  4096

// ---------------- static device scratch ----------------
__device__ __align__(128) __half g_Ah[(size_t)B_ROWS * K_DIM];
__device__ __align__(128) __half g_Al[(size_t)B_ROWS * K_DIM];
__device__ __align__(128) __half g_Bh[(size_t)N_DIM * K_DIM];
__device__ __align__(128) __half g_Bl[(size_t)N_DIM * K_DIM];
__device__ __align__(128) float  g_z[(size_t)B_ROWS * N_DIM];

// ---------------- helpers ----------------
__device__ __forceinline__ uint32_t smem_u32(const void* p) {
    uint32_t a;
    asm("{ .reg .u64 t; cvta.to.shared.u64 t, %1; cvt.u32.u64 %0, t; }" : "=r"(a) : "l"(p));
    return a;
}
__device__ __forceinline__ void cp_async16(uint32_t dst, const void* src) {
    asm volatile("cp.async.cg.shared.global [%0], [%1], 16;" :: "r"(dst), "l"(src) : "memory");
}
__device__ __forceinline__ void cp_commit() {
    asm volatile("cp.async.commit_group;" ::: "memory");
}
template <int N>
__device__ __forceinline__ void cp_wait() {
    asm volatile("cp.async.wait_group %0;" :: "n"(N) : "memory");
}
__device__ __forceinline__ void ldsm4(uint32_t& r0, uint32_t& r1, uint32_t& r2, uint32_t& r3,
                                      uint32_t addr) {
    asm volatile("ldmatrix.sync.aligned.m8n8.x4.shared.b16 {%0,%1,%2,%3}, [%4];"
                 : "=r"(r0), "=r"(r1), "=r"(r2), "=r"(r3) : "r"(addr));
}
__device__ __forceinline__ void mma16816(float& d0, float& d1, float& d2, float& d3,
                                         uint32_t a0, uint32_t a1, uint32_t a2, uint32_t a3,
                                         uint32_t b0, uint32_t b1) {
    asm volatile(
        "mma.sync.aligned.m16n8k16.row.col.f32.f16.f16.f32 "
        "{%0,%1,%2,%3}, {%4,%5,%6,%7}, {%8,%9}, {%0,%1,%2,%3};"
        : "+f"(d0), "+f"(d1), "+f"(d2), "+f"(d3)
        : "r"(a0), "r"(a1), "r"(a2), "r"(a3), "r"(b0), "r"(b1));
}

// ---------------- conversion kernels (fp32 -> fp16 hi/lo split) ----------------
__device__ __forceinline__ void split2(float v, __half& hi, __half& lo) {
    hi = __float2half_rn(v);
    lo = __float2half_rn(v - __half2float(hi));
}

__global__ __launch_bounds__(256) void conv_A(const float* __restrict__ x,
                                              const float* __restrict__ h) {
    size_t e = ((size_t)blockIdx.x * 256 + threadIdx.x) * 4;
    int m = (int)(e >> 11);
    int k = (int)(e & 2047);
    const float* src = (k < 1024) ? &x[(size_t)m * 1024 + k] : &h[(size_t)m * 1024 + (k - 1024)];
    float4 v = *reinterpret_cast<const float4*>(src);
    float vv[4] = {v.x, v.y, v.z, v.w};
    __half hi[4], lo[4];
#pragma unroll
    for (int i = 0; i < 4; i++) split2(vv[i], hi[i], lo[i]);
    *reinterpret_cast<__half2*>(&g_Ah[e])     = __halves2half2(hi[0], hi[1]);
    *reinterpret_cast<__half2*>(&g_Ah[e + 2]) = __halves2half2(hi[2], hi[3]);
    *reinterpret_cast<__half2*>(&g_Al[e])     = __halves2half2(lo[0], lo[1]);
    *reinterpret_cast<__half2*>(&g_Al[e + 2]) = __halves2half2(lo[2], lo[3]);
}

__global__ __launch_bounds__(256) void conv_B(const float* __restrict__ Wi,
                                              const float* __restrict__ Wf,
                                              const float* __restrict__ Wc,
                                              const float* __restrict__ Wo) {
    size_t e = ((size_t)blockIdx.x * 256 + threadIdx.x) * 4;
    int n = (int)(e >> 11);                    // n = gate*1024 + j (natural order)
    int k = (int)(e & 2047);
    int g = n >> 10;
    int j = n & 1023;
    const float* W = (g == 0) ? Wi : (g == 1) ? Wf : (g == 2) ? Wc : Wo;
    float4 v = *reinterpret_cast<const float4*>(&W[(size_t)j * K_DIM + k]);
    float vv[4] = {v.x, v.y, v.z, v.w};
    __half hi[4], lo[4];
#pragma unroll
    for (int i = 0; i < 4; i++) split2(vv[i], hi[i], lo[i]);
    *reinterpret_cast<__half2*>(&g_Bh[e])     = __halves2half2(hi[0], hi[1]);
    *reinterpret_cast<__half2*>(&g_Bh[e + 2]) = __halves2half2(hi[2], hi[3]);
    *reinterpret_cast<__half2*>(&g_Bl[e])     = __halves2half2(lo[0], lo[1]);
    *reinterpret_cast<__half2*>(&g_Bl[e + 2]) = __halves2half2(lo[2], lo[3]);
}

// ---------------- main GEMM: z = A*B^T  (split fp16, K' = 3*2048) ----------------
// CTA 128x128, BK=64 halves (128B), 4-stage cp.async pipeline, 8 warps (2M x 4N),
// warp tile 64x32 -> mma.m16n8k16, 4 mfrag x 4 nfrag.
#define BK 64
#define STAGES 4
#define TILE_A_BYTES (128 * 128)    // 128 rows x 128B
#define STAGE_BYTES  (2 * TILE_A_BYTES)
#define SMEM_BYTES   (STAGES * STAGE_BYTES)     // 131072
#define NTILES 96                                // 3 segments x 32 k-tiles

__global__ __launch_bounds__(256, 1) void gemm_hmma() {
    extern __shared__ char smem[];
    const uint32_t sbase = smem_u32(smem);
    const int tid = threadIdx.x;
    const int lane = tid & 31;
    const int wid = tid >> 5;
    const int wm = wid & 1;       // 2 warps along M
    const int wn = wid >> 1;      // 4 warps along N

    const int m0 = blockIdx.y * 128;
    const int n0 = blockIdx.x * 128;

    // segment sources: (Ah,Bh), (Al,Bh), (Ah,Bl)
    const __half* segA[3] = {g_Ah, g_Al, g_Ah};
    const __half* segB[3] = {g_Bh, g_Bh, g_Bl};

    // ---- async tile loader: tile t -> stage s ----
    auto load_tile = [&](int t, int s) {
        const int seg = t >> 5;
        const int kt = (t & 31) * BK;
        const __half* Ag = segA[seg];
        const __half* Bg = segB[seg];
        const uint32_t stA = sbase + (uint32_t)s * STAGE_BYTES;
        const uint32_t stB = stA + TILE_A_BYTES;
#pragma unroll
        for (int i = 0; i < 4; i++) {
            int id = i * 256 + tid;            // [0,1024)
            int row = id >> 3;
            int c = id & 7;
            uint32_t soff = (uint32_t)(row * 128) + (uint32_t)(((c ^ (row & 7)) << 4));
            cp_async16(stA + soff, Ag + (size_t)(m0 + row) * K_DIM + kt + c * 8);
            cp_async16(stB + soff, Bg + (size_t)(n0 + row) * K_DIM + kt + c * 8);
        }
        cp_commit();
    };

    float acc[4][4][4];
#pragma unroll
    for (int i = 0; i < 4; i++)
#pragma unroll
        for (int j = 0; j < 4; j++)
#pragma unroll
            for (int q = 0; q < 4; q++) acc[i][j][q] = 0.0f;

    // prologue: fill STAGES-1 stages
#pragma unroll
    for (int p = 0; p < STAGES - 1; p++) load_tile(p, p);

    // per-thread ldmatrix row bases
    // A: row = wm*64 + mf*16 + (lane&15), chunk = 2*kstep + (lane>>4)
    int aRow = wm * 64 + (lane & 15);
    int aHi = lane >> 4;
    // B: row = wn*32 + nf2*16 + (lane&7) + ((lane>>4)<<3), chunk = 2*kstep + ((lane>>3)&1)
    int bRow = wn * 32 + (lane & 7) + ((lane >> 4) << 3);
    int bHi = (lane >> 3) & 1;

    for (int it = 0; it < NTILES; it++) {
        cp_wait<STAGES - 2>();
        __syncthreads();

        if (it + STAGES - 1 < NTILES) load_tile(it + STAGES - 1, (it + STAGES - 1) % STAGES);
        else cp_commit();     // keep group counts consistent

        const uint32_t stA = sbase + (uint32_t)(it % STAGES) * STAGE_BYTES;
        const uint32_t stB = stA + TILE_A_BYTES;

#pragma unroll
        for (int ks = 0; ks < BK / 16; ks++) {
            uint32_t a[4][4];
#pragma unroll
            for (int mf = 0; mf < 4; mf++) {
                int row = aRow + mf * 16;
                int c = 2 * ks + aHi;
                uint32_t addr = stA + row * 128 + (((c ^ (row & 7)) << 4));
                ldsm4(a[mf][0], a[mf][1], a[mf][2], a[mf][3], addr);
            }
            uint32_t b[4][2];
#pragma unroll
            for (int nf2 = 0; nf2 < 2; nf2++) {
                int row = bRow + nf2 * 16;
                int c = 2 * ks + bHi;
                uint32_t addr = stB + row * 128 + (((c ^ (row & 7)) << 4));
                uint32_t r0, r1, r2, r3;
                ldsm4(r0, r1, r2, r3, addr);
                b[nf2 * 2 + 0][0] = r0; b[nf2 * 2 + 0][1] = r1;
                b[nf2 * 2 + 1][0] = r2; b[nf2 * 2 + 1][1] = r3;
            }
#pragma unroll
            for (int mf = 0; mf < 4; mf++)
#pragma unroll
                for (int nf = 0; nf < 4; nf++)
                    mma16816(acc[mf][nf][0], acc[mf][nf][1], acc[mf][nf][2], acc[mf][nf][3],
                             a[mf][0], a[mf][1], a[mf][2], a[mf][3],
                             b[nf][0], b[nf][1]);
        }
        __syncthreads();
    }

    // ---- store z ----
#pragma unroll
    for (int mf = 0; mf < 4; mf++) {
#pragma unroll
        for (int nf = 0; nf < 4; nf++) {
            int m = m0 + wm * 64 + mf * 16 + (lane >> 2);
            int n = n0 + wn * 32 + nf * 8 + 2 * (lane & 3);
            float* p0 = &g_z[(size_t)m * N_DIM + n];
            float* p1 = &g_z[(size_t)(m + 8) * N_DIM + n];
            *reinterpret_cast<float2*>(p0) = make_float2(acc[mf][nf][0], acc[mf][nf][1]);
            *reinterpret_cast<float2*>(p1) = make_float2(acc[mf][nf][2], acc[mf][nf][3]);
        }
    }
}

// ---------------- gate epilogue ----------------
__global__ __launch_bounds__(256) void lstm_epilogue(
    const float* __restrict__ cprev,
    const float* __restrict__ bi, const float* __restrict__ bf_,
    const float* __restrict__ bc, const float* __restrict__ bo,
    float* __restrict__ out)
{
    const int idx = blockIdx.x * blockDim.x + threadIdx.x;   // [0, B*D_H)
    const int m = idx >> 10;
    const int j = idx & 1023;
    const size_t base = (size_t)m * N_DIM + j;

    const float zi = g_z[base]        + bi[j];
    const float zf = g_z[base + 1024] + bf_[j];
    const float zc = g_z[base + 2048] + bc[j];
    const float zo = g_z[base + 3072] + bo[j];

    const float ig = 1.0f / (1.0f + expf(-zi));
    const float fg = 1.0f / (1.0f + expf(-zf));
    const float cg = tanhf(zc);
    const float og = 1.0f / (1.0f + expf(-zo));

    const float cn = fg * cprev[idx] + ig * cg;
    const float hn = og * tanhf(cn);

    out[idx] = hn;
    out[(size_t)B_ROWS * D_H + idx] = cn;
}

// ---------------- launch ----------------
extern "C" void kernel_launch(void* const* d_in, const int* in_sizes, int n_in,
                              void* d_out, int out_size)
{
    const float* x  = (const float*)d_in[0];
    const float* h  = (const float*)d_in[1];
    const float* c  = (const float*)d_in[2];
    const float* Wi = (const float*)d_in[3];
    const float* bi = (const float*)d_in[4];
    const float* Wf = (const float*)d_in[5];
    const float* bf = (const float*)d_in[6];
    const float* Wc = (const float*)d_in[7];
    const float* bc = (const float*)d_in[8];
    const float* Wo = (const float*)d_in[9];
    const float* bo = (const float*)d_in[10];
    float* out = (float*)d_out;

    static bool attr_set = false;
    if (!attr_set) {
        cudaFuncSetAttribute(gemm_hmma, cudaFuncAttributeMaxDynamicSharedMemorySize, SMEM_BYTES);
        attr_set = true;
    }

    conv_A<<<(B_ROWS * K_DIM / 4) / 256, 256>>>(x, h);
    conv_B<<<(N_DIM * K_DIM / 4) / 256, 256>>>(Wi, Wf, Wc, Wo);

    dim3 grid(N_DIM / 128, B_ROWS / 128);   // 32 x 32
    gemm_hmma<<<grid, 256, SMEM_BYTES>>>();

    lstm_epilogue<<<(B_ROWS * D_H) / 256, 256>>>(c, bi, bf, bc, bo, out);
}

// round 4
// speedup vs baseline: 3.2229x; 1.0816x over previous
#include <cuda_runtime.h>
#include <cuda_fp16.h>
#include <math.h>
#include <stdint.h>

#define B_ROWS 4096
#define D_H    1024
#define K_DIM  2048
#define N_DIM  4096

// ---------------- static device scratch ----------------
__device__ __align__(128) __half g_Ah[(size_t)B_ROWS * K_DIM];
__device__ __align__(128) __half g_Al[(size_t)B_ROWS * K_DIM];
__device__ __align__(128) __half g_Bh[(size_t)N_DIM * K_DIM];   // interleaved rows n' = 4j+g
__device__ __align__(128) __half g_Bl[(size_t)N_DIM * K_DIM];
__device__ __align__(128) float  g_bias[N_DIM];                 // interleaved

// ---------------- helpers ----------------
__device__ __forceinline__ uint32_t smem_u32(const void* p) {
    uint32_t a;
    asm("{ .reg .u64 t; cvta.to.shared.u64 t, %1; cvt.u32.u64 %0, t; }" : "=r"(a) : "l"(p));
    return a;
}
__device__ __forceinline__ void cp_async16(uint32_t dst, const void* src) {
    asm volatile("cp.async.cg.shared.global [%0], [%1], 16;" :: "r"(dst), "l"(src) : "memory");
}
__device__ __forceinline__ void cp_commit() {
    asm volatile("cp.async.commit_group;" ::: "memory");
}
template <int N>
__device__ __forceinline__ void cp_wait() {
    asm volatile("cp.async.wait_group %0;" :: "n"(N) : "memory");
}
__device__ __forceinline__ void ldsm4(uint32_t& r0, uint32_t& r1, uint32_t& r2, uint32_t& r3,
                                      uint32_t addr) {
    asm volatile("ldmatrix.sync.aligned.m8n8.x4.shared.b16 {%0,%1,%2,%3}, [%4];"
                 : "=r"(r0), "=r"(r1), "=r"(r2), "=r"(r3) : "r"(addr));
}
__device__ __forceinline__ void mma16816(float& d0, float& d1, float& d2, float& d3,
                                         uint32_t a0, uint32_t a1, uint32_t a2, uint32_t a3,
                                         uint32_t b0, uint32_t b1) {
    asm volatile(
        "mma.sync.aligned.m16n8k16.row.col.f32.f16.f16.f32 "
        "{%0,%1,%2,%3}, {%4,%5,%6,%7}, {%8,%9}, {%0,%1,%2,%3};"
        : "+f"(d0), "+f"(d1), "+f"(d2), "+f"(d3)
        : "r"(a0), "r"(a1), "r"(a2), "r"(a3), "r"(b0), "r"(b1));
}

// ---------------- conversion kernels ----------------
__device__ __forceinline__ void split2(float v, __half& hi, __half& lo) {
    hi = __float2half_rn(v);
    lo = __float2half_rn(v - __half2float(hi));
}

__global__ __launch_bounds__(256) void conv_A(const float* __restrict__ x,
                                              const float* __restrict__ h) {
    size_t e = ((size_t)blockIdx.x * 256 + threadIdx.x) * 4;
    int m = (int)(e >> 11);
    int k = (int)(e & 2047);
    const float* src = (k < 1024) ? &x[(size_t)m * 1024 + k] : &h[(size_t)m * 1024 + (k - 1024)];
    float4 v = *reinterpret_cast<const float4*>(src);
    float vv[4] = {v.x, v.y, v.z, v.w};
    __half hi[4], lo[4];
#pragma unroll
    for (int i = 0; i < 4; i++) split2(vv[i], hi[i], lo[i]);
    *reinterpret_cast<__half2*>(&g_Ah[e])     = __halves2half2(hi[0], hi[1]);
    *reinterpret_cast<__half2*>(&g_Ah[e + 2]) = __halves2half2(hi[2], hi[3]);
    *reinterpret_cast<__half2*>(&g_Al[e])     = __halves2half2(lo[0], lo[1]);
    *reinterpret_cast<__half2*>(&g_Al[e + 2]) = __halves2half2(lo[2], lo[3]);
}

__global__ __launch_bounds__(256) void conv_B(const float* __restrict__ Wi,
                                              const float* __restrict__ Wf,
                                              const float* __restrict__ Wc,
                                              const float* __restrict__ Wo) {
    size_t e = ((size_t)blockIdx.x * 256 + threadIdx.x) * 4;
    int np = (int)(e >> 11);     // n' = 4*j + gate (interleaved)
    int k = (int)(e & 2047);
    int j = np >> 2;
    int g = np & 3;
    const float* W = (g == 0) ? Wi : (g == 1) ? Wf : (g == 2) ? Wc : Wo;
    float4 v = *reinterpret_cast<const float4*>(&W[(size_t)j * K_DIM + k]);
    float vv[4] = {v.x, v.y, v.z, v.w};
    __half hi[4], lo[4];
#pragma unroll
    for (int i = 0; i < 4; i++) split2(vv[i], hi[i], lo[i]);
    *reinterpret_cast<__half2*>(&g_Bh[e])     = __halves2half2(hi[0], hi[1]);
    *reinterpret_cast<__half2*>(&g_Bh[e + 2]) = __halves2half2(hi[2], hi[3]);
    *reinterpret_cast<__half2*>(&g_Bl[e])     = __halves2half2(lo[0], lo[1]);
    *reinterpret_cast<__half2*>(&g_Bl[e + 2]) = __halves2half2(lo[2], lo[3]);
}

__global__ __launch_bounds__(256) void conv_bias(const float* __restrict__ bi,
                                                 const float* __restrict__ bf_,
                                                 const float* __restrict__ bc,
                                                 const float* __restrict__ bo) {
    int idx = blockIdx.x * 256 + threadIdx.x;
    int j = idx >> 2;
    int g = idx & 3;
    g_bias[idx] = (g == 0) ? bi[j] : (g == 1) ? bf_[j] : (g == 2) ? bc[j] : bo[j];
}

// ---------------- fused GEMM + LSTM ----------------
// CTA 128(M) x 256(N'), 8 warps 2Mx4N, warp tile 64x64, BK=64, 2-stage cp.async.
// 3 split products with fragment reuse: Ah*Bh, Al*Bh, Ah*Bl.
#define BK 64
#define STAGES 2
#define OFF_AH 0
#define OFF_AL 16384
#define OFF_BH 32768
#define OFF_BL 65536
#define STAGE_BYTES 98304          // (128+128+256+256) rows x 128B
#define BIAS_OFF    (2 * STAGE_BYTES)
#define SMEM_TOTAL  (BIAS_OFF + 1024)   // 197632
#define NKT (K_DIM / BK)           // 32
#define OUT_C_OFF ((size_t)B_ROWS * D_H)

__global__ __launch_bounds__(256, 1) void lstm_fused(const float* __restrict__ cprev,
                                                     float* __restrict__ out) {
    extern __shared__ char smem[];
    const uint32_t sbase = smem_u32(smem);
    const int tid = threadIdx.x;
    const int lane = tid & 31;
    const int wid = tid >> 5;
    const int wm = wid & 1;            // 2 warps along M
    const int wn = wid >> 1;           // 4 warps along N
    const int aw = wm * 64;
    const int bw = wn * 64;

    const int m0 = blockIdx.y * 128;
    const int n0 = blockIdx.x * 256;   // in n' units

    // bias for this CTA's 256 n' columns
    float* bias_s = reinterpret_cast<float*>(smem + BIAS_OFF);
    if (tid < 256) bias_s[tid] = g_bias[n0 + tid];

    // ---- async stage loader ----
    auto load_stage = [&](int it, int s) {
        const int kt = it * BK;
        const uint32_t st = sbase + (uint32_t)s * STAGE_BYTES;
#pragma unroll
        for (int i = 0; i < 4; i++) {                        // Ah, Al: 128 rows
            int id = i * 256 + tid;
            int row = id >> 3, c = id & 7;
            uint32_t so = (uint32_t)(row * 128) + (uint32_t)((c ^ (row & 7)) << 4);
            const size_t goff = (size_t)(m0 + row) * K_DIM + kt + c * 8;
            cp_async16(st + OFF_AH + so, g_Ah + goff);
            cp_async16(st + OFF_AL + so, g_Al + goff);
        }
#pragma unroll
        for (int i = 0; i < 8; i++) {                        // Bh, Bl: 256 rows
            int id = i * 256 + tid;
            int row = id >> 3, c = id & 7;
            uint32_t so = (uint32_t)(row * 128) + (uint32_t)((c ^ (row & 7)) << 4);
            const size_t goff = (size_t)(n0 + row) * K_DIM + kt + c * 8;
            cp_async16(st + OFF_BH + so, g_Bh + goff);
            cp_async16(st + OFF_BL + so, g_Bl + goff);
        }
        cp_commit();
    };

    float acc[4][8][4];
#pragma unroll
    for (int i = 0; i < 4; i++)
#pragma unroll
        for (int j = 0; j < 8; j++)
#pragma unroll
            for (int q = 0; q < 4; q++) acc[i][j][q] = 0.0f;

    load_stage(0, 0);
    load_stage(1, 1);

    const int aRow = aw + (lane & 15);
    const int aHi = lane >> 4;
    const int bRow = bw + (lane & 7) + ((lane >> 4) << 3);
    const int bHi = (lane >> 3) & 1;

    for (int it = 0; it < NKT; it++) {
        cp_wait<1>();
        __syncthreads();

        const uint32_t st = sbase + (uint32_t)(it & 1) * STAGE_BYTES;

#pragma unroll
        for (int ks = 0; ks < BK / 16; ks++) {
            uint32_t aH[4][4], bH[8][2];
#pragma unroll
            for (int mf = 0; mf < 4; mf++) {
                int row = aRow + mf * 16;
                int c = 2 * ks + aHi;
                uint32_t addr = st + OFF_AH + row * 128 + ((c ^ (row & 7)) << 4);
                ldsm4(aH[mf][0], aH[mf][1], aH[mf][2], aH[mf][3], addr);
            }
#pragma unroll
            for (int nf2 = 0; nf2 < 4; nf2++) {
                int row = bRow + nf2 * 16;
                int c = 2 * ks + bHi;
                uint32_t addr = st + OFF_BH + row * 128 + ((c ^ (row & 7)) << 4);
                ldsm4(bH[2 * nf2][0], bH[2 * nf2][1], bH[2 * nf2 + 1][0], bH[2 * nf2 + 1][1], addr);
            }
            // P1: Ah * Bh
#pragma unroll
            for (int mf = 0; mf < 4; mf++)
#pragma unroll
                for (int nf = 0; nf < 8; nf++)
                    mma16816(acc[mf][nf][0], acc[mf][nf][1], acc[mf][nf][2], acc[mf][nf][3],
                             aH[mf][0], aH[mf][1], aH[mf][2], aH[mf][3], bH[nf][0], bH[nf][1]);
            // P2: Al * Bh (reuse bH)
            {
                uint32_t aL[4][4];
#pragma unroll
                for (int mf = 0; mf < 4; mf++) {
                    int row = aRow + mf * 16;
                    int c = 2 * ks + aHi;
                    uint32_t addr = st + OFF_AL + row * 128 + ((c ^ (row & 7)) << 4);
                    ldsm4(aL[mf][0], aL[mf][1], aL[mf][2], aL[mf][3], addr);
                }
#pragma unroll
                for (int mf = 0; mf < 4; mf++)
#pragma unroll
                    for (int nf = 0; nf < 8; nf++)
                        mma16816(acc[mf][nf][0], acc[mf][nf][1], acc[mf][nf][2], acc[mf][nf][3],
                                 aL[mf][0], aL[mf][1], aL[mf][2], aL[mf][3], bH[nf][0], bH[nf][1]);
            }
            // P3: Ah * Bl (reuse aH)
            {
                uint32_t bL[8][2];
#pragma unroll
                for (int nf2 = 0; nf2 < 4; nf2++) {
                    int row = bRow + nf2 * 16;
                    int c = 2 * ks + bHi;
                    uint32_t addr = st + OFF_BL + row * 128 + ((c ^ (row & 7)) << 4);
                    ldsm4(bL[2 * nf2][0], bL[2 * nf2][1], bL[2 * nf2 + 1][0], bL[2 * nf2 + 1][1], addr);
                }
#pragma unroll
                for (int mf = 0; mf < 4; mf++)
#pragma unroll
                    for (int nf = 0; nf < 8; nf++)
                        mma16816(acc[mf][nf][0], acc[mf][nf][1], acc[mf][nf][2], acc[mf][nf][3],
                                 aH[mf][0], aH[mf][1], aH[mf][2], aH[mf][3], bL[nf][0], bL[nf][1]);
            }
        }
        __syncthreads();
        if (it + 2 < NKT) load_stage(it + 2, it & 1);
        else cp_commit();
    }

    // ---- fused epilogue: stage acc to smem (bank-swizzled), then gates ----
    float* zs = reinterpret_cast<float*>(smem);      // 128 x 256 fp32 = 128KB
#pragma unroll
    for (int mf = 0; mf < 4; mf++) {
#pragma unroll
        for (int nf = 0; nf < 8; nf++) {
            int r0 = aw + mf * 16 + (lane >> 2);
            int col = bw + nf * 8 + 2 * (lane & 3);
            int c0 = col ^ ((r0 & 7) << 3);
            int c1 = col ^ (((r0 + 8) & 7) << 3);
            *reinterpret_cast<float2*>(&zs[(size_t)r0 * 256 + c0]) =
                make_float2(acc[mf][nf][0], acc[mf][nf][1]);
            *reinterpret_cast<float2*>(&zs[(size_t)(r0 + 8) * 256 + c1]) =
                make_float2(acc[mf][nf][2], acc[mf][nf][3]);
        }
    }
    __syncthreads();

    const int jbase = n0 >> 2;                       // 64 hidden units per CTA
#pragma unroll 4
    for (int r = 0; r < 32; r++) {
        int idx = r * 256 + tid;                     // [0, 8192) quadruples
        int ml = idx >> 6;
        int q = idx & 63;
        int cc = (4 * q) ^ ((ml & 7) << 3);
        float4 z4 = *reinterpret_cast<const float4*>(&zs[(size_t)ml * 256 + cc]);
        float zi = z4.x + bias_s[4 * q + 0];
        float zf = z4.y + bias_s[4 * q + 1];
        float zc = z4.z + bias_s[4 * q + 2];
        float zo = z4.w + bias_s[4 * q + 3];
        int m = m0 + ml;
        int j = jbase + q;
        float cp = cprev[(size_t)m * D_H + j];
        float ig = 1.0f / (1.0f + expf(-zi));
        float fg = 1.0f / (1.0f + expf(-zf));
        float cg = tanhf(zc);
        float og = 1.0f / (1.0f + expf(-zo));
        float cn = fg * cp + ig * cg;
        float hn = og * tanhf(cn);
        out[(size_t)m * D_H + j] = hn;
        out[OUT_C_OFF + (size_t)m * D_H + j] = cn;
    }
}

// ---------------- launch ----------------
extern "C" void kernel_launch(void* const* d_in, const int* in_sizes, int n_in,
                              void* d_out, int out_size)
{
    const float* x  = (const float*)d_in[0];
    const float* h  = (const float*)d_in[1];
    const float* c  = (const float*)d_in[2];
    const float* Wi = (const float*)d_in[3];
    const float* bi = (const float*)d_in[4];
    const float* Wf = (const float*)d_in[5];
    const float* bf = (const float*)d_in[6];
    const float* Wc = (const float*)d_in[7];
    const float* bc = (const float*)d_in[8];
    const float* Wo = (const float*)d_in[9];
    const float* bo = (const float*)d_in[10];
    float* out = (float*)d_out;

    static bool attr_set = false;
    if (!attr_set) {
        cudaFuncSetAttribute(lstm_fused, cudaFuncAttributeMaxDynamicSharedMemorySize, SMEM_TOTAL);
        attr_set = true;
    }

    conv_A<<<(B_ROWS * K_DIM / 4) / 256, 256>>>(x, h);
    conv_B<<<(N_DIM * K_DIM / 4) / 256, 256>>>(Wi, Wf, Wc, Wo);
    conv_bias<<<N_DIM / 256, 256>>>(bi, bf, bc, bo);

    dim3 grid(N_DIM / 256, B_ROWS / 128);   // 16 x 32 = 512 CTAs
    lstm_fused<<<grid, 256, SMEM_TOTAL>>>(c, out);
}

// round 5
// speedup vs baseline: 4.4365x; 1.3765x over previous
#include <cuda_runtime.h>
#include <cuda_fp16.h>
#include <math.h>
#include <stdint.h>

#define B_ROWS 4096
#define D_H    1024
#define K_DIM  2048
#define N_DIM  4096

// ---------------- static device scratch ----------------
__device__ __align__(128) __half g_Ah[(size_t)B_ROWS * K_DIM];
__device__ __align__(128) __half g_Al[(size_t)B_ROWS * K_DIM];
__device__ __align__(128) __half g_Bh[(size_t)N_DIM * K_DIM];   // interleaved rows n' = 4j+g
__device__ __align__(128) float  g_bias[N_DIM];                 // interleaved

// ---------------- helpers ----------------
__device__ __forceinline__ uint32_t smem_u32(const void* p) {
    uint32_t a;
    asm("{ .reg .u64 t; cvta.to.shared.u64 t, %1; cvt.u32.u64 %0, t; }" : "=r"(a) : "l"(p));
    return a;
}
__device__ __forceinline__ void cp_async16(uint32_t dst, const void* src) {
    asm volatile("cp.async.cg.shared.global [%0], [%1], 16;" :: "r"(dst), "l"(src) : "memory");
}
__device__ __forceinline__ void cp_commit() {
    asm volatile("cp.async.commit_group;" ::: "memory");
}
template <int N>
__device__ __forceinline__ void cp_wait() {
    asm volatile("cp.async.wait_group %0;" :: "n"(N) : "memory");
}
__device__ __forceinline__ void ldsm4(uint32_t& r0, uint32_t& r1, uint32_t& r2, uint32_t& r3,
                                      uint32_t addr) {
    asm volatile("ldmatrix.sync.aligned.m8n8.x4.shared.b16 {%0,%1,%2,%3}, [%4];"
                 : "=r"(r0), "=r"(r1), "=r"(r2), "=r"(r3) : "r"(addr));
}
__device__ __forceinline__ void mma16816(float& d0, float& d1, float& d2, float& d3,
                                         uint32_t a0, uint32_t a1, uint32_t a2, uint32_t a3,
                                         uint32_t b0, uint32_t b1) {
    asm volatile(
        "mma.sync.aligned.m16n8k16.row.col.f32.f16.f16.f32 "
        "{%0,%1,%2,%3}, {%4,%5,%6,%7}, {%8,%9}, {%0,%1,%2,%3};"
        : "+f"(d0), "+f"(d1), "+f"(d2), "+f"(d3)
        : "r"(a0), "r"(a1), "r"(a2), "r"(a3), "r"(b0), "r"(b1));
}

// ---------------- conversion kernels ----------------
__global__ __launch_bounds__(256) void conv_A(const float* __restrict__ x,
                                              const float* __restrict__ h) {
    size_t e = ((size_t)blockIdx.x * 256 + threadIdx.x) * 4;
    int m = (int)(e >> 11);
    int k = (int)(e & 2047);
    const float* src = (k < 1024) ? &x[(size_t)m * 1024 + k] : &h[(size_t)m * 1024 + (k - 1024)];
    float4 v = *reinterpret_cast<const float4*>(src);
    float vv[4] = {v.x, v.y, v.z, v.w};
    __half hi[4], lo[4];
#pragma unroll
    for (int i = 0; i < 4; i++) {
        hi[i] = __float2half_rn(vv[i]);
        lo[i] = __float2half_rn(vv[i] - __half2float(hi[i]));
    }
    *reinterpret_cast<__half2*>(&g_Ah[e])     = __halves2half2(hi[0], hi[1]);
    *reinterpret_cast<__half2*>(&g_Ah[e + 2]) = __halves2half2(hi[2], hi[3]);
    *reinterpret_cast<__half2*>(&g_Al[e])     = __halves2half2(lo[0], lo[1]);
    *reinterpret_cast<__half2*>(&g_Al[e + 2]) = __halves2half2(lo[2], lo[3]);
}

__global__ __launch_bounds__(256) void conv_B(const float* __restrict__ Wi,
                                              const float* __restrict__ Wf,
                                              const float* __restrict__ Wc,
                                              const float* __restrict__ Wo) {
    size_t e = ((size_t)blockIdx.x * 256 + threadIdx.x) * 4;
    int np = (int)(e >> 11);     // n' = 4*j + gate (interleaved)
    int k = (int)(e & 2047);
    int j = np >> 2;
    int g = np & 3;
    const float* W = (g == 0) ? Wi : (g == 1) ? Wf : (g == 2) ? Wc : Wo;
    float4 v = *reinterpret_cast<const float4*>(&W[(size_t)j * K_DIM + k]);
    __half2 h01 = __halves2half2(__float2half_rn(v.x), __float2half_rn(v.y));
    __half2 h23 = __halves2half2(__float2half_rn(v.z), __float2half_rn(v.w));
    *reinterpret_cast<__half2*>(&g_Bh[e])     = h01;
    *reinterpret_cast<__half2*>(&g_Bh[e + 2]) = h23;
}

__global__ __launch_bounds__(256) void conv_bias(const float* __restrict__ bi,
                                                 const float* __restrict__ bf_,
                                                 const float* __restrict__ bc,
                                                 const float* __restrict__ bo) {
    int idx = blockIdx.x * 256 + threadIdx.x;
    int j = idx >> 2;
    int g = idx & 3;
    g_bias[idx] = (g == 0) ? bi[j] : (g == 1) ? bf_[j] : (g == 2) ? bc[j] : bo[j];
}

// ---------------- fused GEMM + LSTM ----------------
// CTA 128(M) x 256(N'), 8 warps 2Mx4N, warp tile 64x64, BK=64, 3-stage cp.async.
// 2 split products (exact A at 22 bits, fp16 B): Ah*Bh + Al*Bh.
#define BK 64
#define OFF_AH 0
#define OFF_AL 16384
#define OFF_BH 32768
#define STAGE_BYTES 65536          // (128+128+256) rows x 128B
#define NSTAGES 3
#define BIAS_OFF    (NSTAGES * STAGE_BYTES)     // 196608
#define SMEM_TOTAL  (BIAS_OFF + 1024)           // 197632
#define NKT (K_DIM / BK)           // 32
#define OUT_C_OFF ((size_t)B_ROWS * D_H)

__global__ __launch_bounds__(256, 1) void lstm_fused(const float* __restrict__ cprev,
                                                     float* __restrict__ out) {
    extern __shared__ char smem[];
    const uint32_t sbase = smem_u32(smem);
    const int tid = threadIdx.x;
    const int lane = tid & 31;
    const int wid = tid >> 5;
    const int wm = wid & 1;            // 2 warps along M
    const int wn = wid >> 1;           // 4 warps along N
    const int aw = wm * 64;
    const int bw = wn * 64;

    const int m0 = blockIdx.y * 128;
    const int n0 = blockIdx.x * 256;   // in n' units

    float* bias_s = reinterpret_cast<float*>(smem + BIAS_OFF);
    if (tid < 256) bias_s[tid] = g_bias[n0 + tid];

    // ---- async stage loader: Ah(128r) + Al(128r) + Bh(256r), 128B rows ----
    auto load_stage = [&](int it, int s) {
        const int kt = it * BK;
        const uint32_t st = sbase + (uint32_t)s * STAGE_BYTES;
#pragma unroll
        for (int i = 0; i < 4; i++) {                        // Ah, Al: 128 rows
            int id = i * 256 + tid;
            int row = id >> 3, c = id & 7;
            uint32_t so = (uint32_t)(row * 128) + (uint32_t)((c ^ (row & 7)) << 4);
            const size_t goff = (size_t)(m0 + row) * K_DIM + kt + c * 8;
            cp_async16(st + OFF_AH + so, g_Ah + goff);
            cp_async16(st + OFF_AL + so, g_Al + goff);
        }
#pragma unroll
        for (int i = 0; i < 8; i++) {                        // Bh: 256 rows
            int id = i * 256 + tid;
            int row = id >> 3, c = id & 7;
            uint32_t so = (uint32_t)(row * 128) + (uint32_t)((c ^ (row & 7)) << 4);
            cp_async16(st + OFF_BH + so, g_Bh + (size_t)(n0 + row) * K_DIM + kt + c * 8);
        }
        cp_commit();
    };

    float acc[4][8][4];
#pragma unroll
    for (int i = 0; i < 4; i++)
#pragma unroll
        for (int j = 0; j < 8; j++)
#pragma unroll
            for (int q = 0; q < 4; q++) acc[i][j][q] = 0.0f;

    load_stage(0, 0);
    load_stage(1, 1);
    load_stage(2, 2);

    const int aRow = aw + (lane & 15);
    const int aHi = lane >> 4;
    const int bRow = bw + (lane & 7) + ((lane >> 4) << 3);
    const int bHi = (lane >> 3) & 1;

    for (int it = 0; it < NKT; it++) {
        cp_wait<NSTAGES - 1>();
        __syncthreads();

        const uint32_t st = sbase + (uint32_t)(it % NSTAGES) * STAGE_BYTES;

#pragma unroll
        for (int ks = 0; ks < BK / 16; ks++) {
            uint32_t aH[4][4], aL[4][4], bH[8][2];
#pragma unroll
            for (int mf = 0; mf < 4; mf++) {
                int row = aRow + mf * 16;
                int c = 2 * ks + aHi;
                uint32_t off = row * 128 + ((c ^ (row & 7)) << 4);
                ldsm4(aH[mf][0], aH[mf][1], aH[mf][2], aH[mf][3], st + OFF_AH + off);
                ldsm4(aL[mf][0], aL[mf][1], aL[mf][2], aL[mf][3], st + OFF_AL + off);
            }
#pragma unroll
            for (int nf2 = 0; nf2 < 4; nf2++) {
                int row = bRow + nf2 * 16;
                int c = 2 * ks + bHi;
                uint32_t addr = st + OFF_BH + row * 128 + ((c ^ (row & 7)) << 4);
                ldsm4(bH[2 * nf2][0], bH[2 * nf2][1], bH[2 * nf2 + 1][0], bH[2 * nf2 + 1][1], addr);
            }
            // P1: Ah * Bh
#pragma unroll
            for (int mf = 0; mf < 4; mf++)
#pragma unroll
                for (int nf = 0; nf < 8; nf++)
                    mma16816(acc[mf][nf][0], acc[mf][nf][1], acc[mf][nf][2], acc[mf][nf][3],
                             aH[mf][0], aH[mf][1], aH[mf][2], aH[mf][3], bH[nf][0], bH[nf][1]);
            // P2: Al * Bh
#pragma unroll
            for (int mf = 0; mf < 4; mf++)
#pragma unroll
                for (int nf = 0; nf < 8; nf++)
                    mma16816(acc[mf][nf][0], acc[mf][nf][1], acc[mf][nf][2], acc[mf][nf][3],
                             aL[mf][0], aL[mf][1], aL[mf][2], aL[mf][3], bH[nf][0], bH[nf][1]);
        }
        __syncthreads();
        if (it + NSTAGES < NKT) load_stage(it + NSTAGES, (it + NSTAGES) % NSTAGES);
        else cp_commit();
    }

    // ---- fused epilogue: stage acc to smem (bank-swizzled), then gates ----
    float* zs = reinterpret_cast<float*>(smem);      // 128 x 256 fp32 = 128KB
#pragma unroll
    for (int mf = 0; mf < 4; mf++) {
#pragma unroll
        for (int nf = 0; nf < 8; nf++) {
            int r0 = aw + mf * 16 + (lane >> 2);
            int col = bw + nf * 8 + 2 * (lane & 3);
            int c0 = col ^ ((r0 & 7) << 3);
            int c1 = col ^ (((r0 + 8) & 7) << 3);
            *reinterpret_cast<float2*>(&zs[(size_t)r0 * 256 + c0]) =
                make_float2(acc[mf][nf][0], acc[mf][nf][1]);
            *reinterpret_cast<float2*>(&zs[(size_t)(r0 + 8) * 256 + c1]) =
                make_float2(acc[mf][nf][2], acc[mf][nf][3]);
        }
    }
    __syncthreads();

    const int jbase = n0 >> 2;                       // 64 hidden units per CTA
#pragma unroll 4
    for (int r = 0; r < 32; r++) {
        int idx = r * 256 + tid;                     // [0, 8192) quadruples
        int ml = idx >> 6;
        int q = idx & 63;
        int cc = (4 * q) ^ ((ml & 7) << 3);
        float4 z4 = *reinterpret_cast<const float4*>(&zs[(size_t)ml * 256 + cc]);
        float zi = z4.x + bias_s[4 * q + 0];
        float zf = z4.y + bias_s[4 * q + 1];
        float zc = z4.z + bias_s[4 * q + 2];
        float zo = z4.w + bias_s[4 * q + 3];
        int m = m0 + ml;
        int j = jbase + q;
        float cp = cprev[(size_t)m * D_H + j];
        float ig = 1.0f / (1.0f + expf(-zi));
        float fg = 1.0f / (1.0f + expf(-zf));
        float cg = tanhf(zc);
        float og = 1.0f / (1.0f + expf(-zo));
        float cn = fg * cp + ig * cg;
        float hn = og * tanhf(cn);
        out[(size_t)m * D_H + j] = hn;
        out[OUT_C_OFF + (size_t)m * D_H + j] = cn;
    }
}

// ---------------- launch ----------------
extern "C" void kernel_launch(void* const* d_in, const int* in_sizes, int n_in,
                              void* d_out, int out_size)
{
    const float* x  = (const float*)d_in[0];
    const float* h  = (const float*)d_in[1];
    const float* c  = (const float*)d_in[2];
    const float* Wi = (const float*)d_in[3];
    const float* bi = (const float*)d_in[4];
    const float* Wf = (const float*)d_in[5];
    const float* bf = (const float*)d_in[6];
    const float* Wc = (const float*)d_in[7];
    const float* bc = (const float*)d_in[8];
    const float* Wo = (const float*)d_in[9];
    const float* bo = (const float*)d_in[10];
    float* out = (float*)d_out;

    static bool attr_set = false;
    if (!attr_set) {
        cudaFuncSetAttribute(lstm_fused, cudaFuncAttributeMaxDynamicSharedMemorySize, SMEM_TOTAL);
        attr_set = true;
    }

    conv_A<<<(B_ROWS * K_DIM / 4) / 256, 256>>>(x, h);
    conv_B<<<(N_DIM * K_DIM / 4) / 256, 256>>>(Wi, Wf, Wc, Wo);
    conv_bias<<<N_DIM / 256, 256>>>(bi, bf, bc, bo);

    dim3 grid(N_DIM / 256, B_ROWS / 128);   // 16 x 32 = 512 CTAs
    lstm_fused<<<grid, 256, SMEM_TOTAL>>>(c, out);
}

// round 6
// speedup vs baseline: 6.7102x; 1.5125x over previous
#include <cuda_runtime.h>
#include <cuda_fp16.h>
#include <math.h>
#include <stdint.h>

#define B_ROWS 4096
#define D_H    1024
#define K_DIM  2048
#define N_DIM  4096

// ---------------- static device scratch ----------------
__device__ __align__(128) __half g_Ah[(size_t)B_ROWS * K_DIM];
__device__ __align__(128) __half g_Bh[(size_t)N_DIM * K_DIM];   // interleaved rows n' = 4j+g
__device__ __align__(128) float  g_bias[N_DIM];                 // interleaved

// ---------------- helpers ----------------
__device__ __forceinline__ uint32_t smem_u32(const void* p) {
    uint32_t a;
    asm("{ .reg .u64 t; cvta.to.shared.u64 t, %1; cvt.u32.u64 %0, t; }" : "=r"(a) : "l"(p));
    return a;
}
__device__ __forceinline__ void cp_async16(uint32_t dst, const void* src) {
    asm volatile("cp.async.cg.shared.global [%0], [%1], 16;" :: "r"(dst), "l"(src) : "memory");
}
__device__ __forceinline__ void cp_commit() {
    asm volatile("cp.async.commit_group;" ::: "memory");
}
template <int N>
__device__ __forceinline__ void cp_wait() {
    asm volatile("cp.async.wait_group %0;" :: "n"(N) : "memory");
}
__device__ __forceinline__ void ldsm4(uint32_t& r0, uint32_t& r1, uint32_t& r2, uint32_t& r3,
                                      uint32_t addr) {
    asm volatile("ldmatrix.sync.aligned.m8n8.x4.shared.b16 {%0,%1,%2,%3}, [%4];"
                 : "=r"(r0), "=r"(r1), "=r"(r2), "=r"(r3) : "r"(addr));
}
__device__ __forceinline__ void mma16816(float& d0, float& d1, float& d2, float& d3,
                                         uint32_t a0, uint32_t a1, uint32_t a2, uint32_t a3,
                                         uint32_t b0, uint32_t b1) {
    asm volatile(
        "mma.sync.aligned.m16n8k16.row.col.f32.f16.f16.f32 "
        "{%0,%1,%2,%3}, {%4,%5,%6,%7}, {%8,%9}, {%0,%1,%2,%3};"
        : "+f"(d0), "+f"(d1), "+f"(d2), "+f"(d3)
        : "r"(a0), "r"(a1), "r"(a2), "r"(a3), "r"(b0), "r"(b1));
}

// ---------------- conversion kernels ----------------
__global__ __launch_bounds__(256) void conv_A(const float* __restrict__ x,
                                              const float* __restrict__ h) {
    size_t e = ((size_t)blockIdx.x * 256 + threadIdx.x) * 4;
    int m = (int)(e >> 11);
    int k = (int)(e & 2047);
    const float* src = (k < 1024) ? &x[(size_t)m * 1024 + k] : &h[(size_t)m * 1024 + (k - 1024)];
    float4 v = *reinterpret_cast<const float4*>(src);
    *reinterpret_cast<__half2*>(&g_Ah[e])     = __halves2half2(__float2half_rn(v.x), __float2half_rn(v.y));
    *reinterpret_cast<__half2*>(&g_Ah[e + 2]) = __halves2half2(__float2half_rn(v.z), __float2half_rn(v.w));
}

__global__ __launch_bounds__(256) void conv_B(const float* __restrict__ Wi,
                                              const float* __restrict__ Wf,
                                              const float* __restrict__ Wc,
                                              const float* __restrict__ Wo) {
    size_t e = ((size_t)blockIdx.x * 256 + threadIdx.x) * 4;
    int np = (int)(e >> 11);     // n' = 4*j + gate (interleaved)
    int k = (int)(e & 2047);
    int j = np >> 2;
    int g = np & 3;
    const float* W = (g == 0) ? Wi : (g == 1) ? Wf : (g == 2) ? Wc : Wo;
    float4 v = *reinterpret_cast<const float4*>(&W[(size_t)j * K_DIM + k]);
    *reinterpret_cast<__half2*>(&g_Bh[e])     = __halves2half2(__float2half_rn(v.x), __float2half_rn(v.y));
    *reinterpret_cast<__half2*>(&g_Bh[e + 2]) = __halves2half2(__float2half_rn(v.z), __float2half_rn(v.w));
}

__global__ __launch_bounds__(256) void conv_bias(const float* __restrict__ bi,
                                                 const float* __restrict__ bf_,
                                                 const float* __restrict__ bc,
                                                 const float* __restrict__ bo) {
    int idx = blockIdx.x * 256 + threadIdx.x;
    int j = idx >> 2;
    int g = idx & 3;
    g_bias[idx] = (g == 0) ? bi[j] : (g == 1) ? bf_[j] : (g == 2) ? bc[j] : bo[j];
}

// ---------------- fused GEMM + LSTM ----------------
// CTA 128(M) x 256(N'), 8 warps 2Mx4N, warp tile 64x64, BK=64.
// Single fp16 product, 4-stage cp.async pipeline, ONE __syncthreads per K-tile.
#define BK 64
#define OFF_A 0
#define OFF_B 16384
#define STAGE_BYTES 49152          // (128 + 256) rows x 128B
#define NSTAGES 4
#define BIAS_OFF    (NSTAGES * STAGE_BYTES)     // 196608
#define SMEM_TOTAL  (BIAS_OFF + 1024)           // 197632
#define NKT (K_DIM / BK)           // 32
#define OUT_C_OFF ((size_t)B_ROWS * D_H)

__global__ __launch_bounds__(256, 1) void lstm_fused(const float* __restrict__ cprev,
                                                     float* __restrict__ out) {
    extern __shared__ char smem[];
    const uint32_t sbase = smem_u32(smem);
    const int tid = threadIdx.x;
    const int lane = tid & 31;
    const int wid = tid >> 5;
    const int wm = wid & 1;            // 2 warps along M
    const int wn = wid >> 1;           // 4 warps along N
    const int aw = wm * 64;
    const int bw = wn * 64;

    const int m0 = blockIdx.y * 128;
    const int n0 = blockIdx.x * 256;   // in n' units

    float* bias_s = reinterpret_cast<float*>(smem + BIAS_OFF);
    if (tid < 256) bias_s[tid] = g_bias[n0 + tid];

    // ---- async stage loader: Ah(128r) + Bh(256r), 128B swizzled rows ----
    auto load_stage = [&](int it, int s) {
        const int kt = it * BK;
        const uint32_t st = sbase + (uint32_t)s * STAGE_BYTES;
#pragma unroll
        for (int i = 0; i < 4; i++) {                        // Ah: 128 rows
            int id = i * 256 + tid;
            int row = id >> 3, c = id & 7;
            uint32_t so = (uint32_t)(row * 128) + (uint32_t)((c ^ (row & 7)) << 4);
            cp_async16(st + OFF_A + so, g_Ah + (size_t)(m0 + row) * K_DIM + kt + c * 8);
        }
#pragma unroll
        for (int i = 0; i < 8; i++) {                        // Bh: 256 rows
            int id = i * 256 + tid;
            int row = id >> 3, c = id & 7;
            uint32_t so = (uint32_t)(row * 128) + (uint32_t)((c ^ (row & 7)) << 4);
            cp_async16(st + OFF_B + so, g_Bh + (size_t)(n0 + row) * K_DIM + kt + c * 8);
        }
        cp_commit();
    };

    float acc[4][8][4];
#pragma unroll
    for (int i = 0; i < 4; i++)
#pragma unroll
        for (int j = 0; j < 8; j++)
#pragma unroll
            for (int q = 0; q < 4; q++) acc[i][j][q] = 0.0f;

    load_stage(0, 0);
    load_stage(1, 1);
    load_stage(2, 2);

    const int aRow = aw + (lane & 15);
    const int aHi = lane >> 4;
    const int bRow = bw + (lane & 7) + ((lane >> 4) << 3);
    const int bHi = (lane >> 3) & 1;

    for (int it = 0; it < NKT; it++) {
        cp_wait<NSTAGES - 2>();        // stage `it` resident
        __syncthreads();               // also: all warps finished stage it-1

        // refill the slot freed by stage it-1
        if (it + NSTAGES - 1 < NKT) load_stage(it + NSTAGES - 1, (it + NSTAGES - 1) % NSTAGES);

        const uint32_t st = sbase + (uint32_t)(it % NSTAGES) * STAGE_BYTES;

#pragma unroll
        for (int ks = 0; ks < BK / 16; ks++) {
            uint32_t aH[4][4], bH[8][2];
#pragma unroll
            for (int mf = 0; mf < 4; mf++) {
                int row = aRow + mf * 16;
                int c = 2 * ks + aHi;
                uint32_t off = row * 128 + ((c ^ (row & 7)) << 4);
                ldsm4(aH[mf][0], aH[mf][1], aH[mf][2], aH[mf][3], st + OFF_A + off);
            }
#pragma unroll
            for (int nf2 = 0; nf2 < 4; nf2++) {
                int row = bRow + nf2 * 16;
                int c = 2 * ks + bHi;
                uint32_t addr = st + OFF_B + row * 128 + ((c ^ (row & 7)) << 4);
                ldsm4(bH[2 * nf2][0], bH[2 * nf2][1], bH[2 * nf2 + 1][0], bH[2 * nf2 + 1][1], addr);
            }
#pragma unroll
            for (int mf = 0; mf < 4; mf++)
#pragma unroll
                for (int nf = 0; nf < 8; nf++)
                    mma16816(acc[mf][nf][0], acc[mf][nf][1], acc[mf][nf][2], acc[mf][nf][3],
                             aH[mf][0], aH[mf][1], aH[mf][2], aH[mf][3], bH[nf][0], bH[nf][1]);
        }
    }
    __syncthreads();

    // ---- fused epilogue: stage acc to smem (bank-swizzled), then gates ----
    float* zs = reinterpret_cast<float*>(smem);      // 128 x 256 fp32 = 128KB
#pragma unroll
    for (int mf = 0; mf < 4; mf++) {
#pragma unroll
        for (int nf = 0; nf < 8; nf++) {
            int r0 = aw + mf * 16 + (lane >> 2);
            int col = bw + nf * 8 + 2 * (lane & 3);
            int c0 = col ^ ((r0 & 7) << 3);
            int c1 = col ^ (((r0 + 8) & 7) << 3);
            *reinterpret_cast<float2*>(&zs[(size_t)r0 * 256 + c0]) =
                make_float2(acc[mf][nf][0], acc[mf][nf][1]);
            *reinterpret_cast<float2*>(&zs[(size_t)(r0 + 8) * 256 + c1]) =
                make_float2(acc[mf][nf][2], acc[mf][nf][3]);
        }
    }
    __syncthreads();

    const int jbase = n0 >> 2;                       // 64 hidden units per CTA
#pragma unroll 4
    for (int r = 0; r < 32; r++) {
        int idx = r * 256 + tid;                     // [0, 8192) quadruples
        int ml = idx >> 6;
        int q = idx & 63;
        int cc = (4 * q) ^ ((ml & 7) << 3);
        float4 z4 = *reinterpret_cast<const float4*>(&zs[(size_t)ml * 256 + cc]);
        float zi = z4.x + bias_s[4 * q + 0];
        float zf = z4.y + bias_s[4 * q + 1];
        float zc = z4.z + bias_s[4 * q + 2];
        float zo = z4.w + bias_s[4 * q + 3];
        int m = m0 + ml;
        int j = jbase + q;
        float cp = cprev[(size_t)m * D_H + j];
        float ig = 1.0f / (1.0f + expf(-zi));
        float fg = 1.0f / (1.0f + expf(-zf));
        float cg = tanhf(zc);
        float og = 1.0f / (1.0f + expf(-zo));
        float cn = fg * cp + ig * cg;
        float hn = og * tanhf(cn);
        out[(size_t)m * D_H + j] = hn;
        out[OUT_C_OFF + (size_t)m * D_H + j] = cn;
    }
}

// ---------------- launch ----------------
extern "C" void kernel_launch(void* const* d_in, const int* in_sizes, int n_in,
                              void* d_out, int out_size)
{
    const float* x  = (const float*)d_in[0];
    const float* h  = (const float*)d_in[1];
    const float* c  = (const float*)d_in[2];
    const float* Wi = (const float*)d_in[3];
    const float* bi = (const float*)d_in[4];
    const float* Wf = (const float*)d_in[5];
    const float* bf = (const float*)d_in[6];
    const float* Wc = (const float*)d_in[7];
    const float* bc = (const float*)d_in[8];
    const float* Wo = (const float*)d_in[9];
    const float* bo = (const float*)d_in[10];
    float* out = (float*)d_out;

    static bool attr_set = false;
    if (!attr_set) {
        cudaFuncSetAttribute(lstm_fused, cudaFuncAttributeMaxDynamicSharedMemorySize, SMEM_TOTAL);
        attr_set = true;
    }

    conv_A<<<(B_ROWS * K_DIM / 4) / 256, 256>>>(x, h);
    conv_B<<<(N_DIM * K_DIM / 4) / 256, 256>>>(Wi, Wf, Wc, Wo);
    conv_bias<<<N_DIM / 256, 256>>>(bi, bf, bc, bo);

    dim3 grid(N_DIM / 256, B_ROWS / 128);   // 16 x 32 = 512 CTAs
    lstm_fused<<<grid, 256, SMEM_TOTAL>>>(c, out);
}

// round 7
// speedup vs baseline: 7.6519x; 1.1403x over previous
#include <cuda_runtime.h>
#include <cuda_fp16.h>
#include <math.h>
#include <stdint.h>

#define B_ROWS 4096
#define D_H    1024
#define K_DIM  2048
#define N_DIM  4096

// ---------------- static device scratch ----------------
__device__ __align__(128) __half g_Ah[(size_t)B_ROWS * K_DIM];
__device__ __align__(128) __half g_Bh[(size_t)N_DIM * K_DIM];   // interleaved rows n' = 4j+g
__device__ __align__(128) float  g_bias[N_DIM];                 // interleaved

// ---------------- helpers ----------------
__device__ __forceinline__ uint32_t smem_u32(const void* p) {
    uint32_t a;
    asm("{ .reg .u64 t; cvta.to.shared.u64 t, %1; cvt.u32.u64 %0, t; }" : "=r"(a) : "l"(p));
    return a;
}
__device__ __forceinline__ void cp_async16(uint32_t dst, const void* src) {
    asm volatile("cp.async.cg.shared.global [%0], [%1], 16;" :: "r"(dst), "l"(src) : "memory");
}
__device__ __forceinline__ void cp_commit() {
    asm volatile("cp.async.commit_group;" ::: "memory");
}
template <int N>
__device__ __forceinline__ void cp_wait() {
    asm volatile("cp.async.wait_group %0;" :: "n"(N) : "memory");
}
__device__ __forceinline__ void ldsm4(uint32_t& r0, uint32_t& r1, uint32_t& r2, uint32_t& r3,
                                      uint32_t addr) {
    asm volatile("ldmatrix.sync.aligned.m8n8.x4.shared.b16 {%0,%1,%2,%3}, [%4];"
                 : "=r"(r0), "=r"(r1), "=r"(r2), "=r"(r3) : "r"(addr));
}
__device__ __forceinline__ void mma16816(float& d0, float& d1, float& d2, float& d3,
                                         uint32_t a0, uint32_t a1, uint32_t a2, uint32_t a3,
                                         uint32_t b0, uint32_t b1) {
    asm volatile(
        "mma.sync.aligned.m16n8k16.row.col.f32.f16.f16.f32 "
        "{%0,%1,%2,%3}, {%4,%5,%6,%7}, {%8,%9}, {%0,%1,%2,%3};"
        : "+f"(d0), "+f"(d1), "+f"(d2), "+f"(d3)
        : "r"(a0), "r"(a1), "r"(a2), "r"(a3), "r"(b0), "r"(b1));
}

// ---------------- conversion kernels ----------------
__global__ __launch_bounds__(256) void conv_A(const float* __restrict__ x,
                                              const float* __restrict__ h) {
    size_t e = ((size_t)blockIdx.x * 256 + threadIdx.x) * 4;
    int m = (int)(e >> 11);
    int k = (int)(e & 2047);
    const float* src = (k < 1024) ? &x[(size_t)m * 1024 + k] : &h[(size_t)m * 1024 + (k - 1024)];
    float4 v = *reinterpret_cast<const float4*>(src);
    *reinterpret_cast<__half2*>(&g_Ah[e])     = __halves2half2(__float2half_rn(v.x), __float2half_rn(v.y));
    *reinterpret_cast<__half2*>(&g_Ah[e + 2]) = __halves2half2(__float2half_rn(v.z), __float2half_rn(v.w));
}

__global__ __launch_bounds__(256) void conv_B(const float* __restrict__ Wi,
                                              const float* __restrict__ Wf,
                                              const float* __restrict__ Wc,
                                              const float* __restrict__ Wo) {
    size_t e = ((size_t)blockIdx.x * 256 + threadIdx.x) * 4;
    int np = (int)(e >> 11);     // n' = 4*j + gate (interleaved)
    int k = (int)(e & 2047);
    int j = np >> 2;
    int g = np & 3;
    const float* W = (g == 0) ? Wi : (g == 1) ? Wf : (g == 2) ? Wc : Wo;
    float4 v = *reinterpret_cast<const float4*>(&W[(size_t)j * K_DIM + k]);
    *reinterpret_cast<__half2*>(&g_Bh[e])     = __halves2half2(__float2half_rn(v.x), __float2half_rn(v.y));
    *reinterpret_cast<__half2*>(&g_Bh[e + 2]) = __halves2half2(__float2half_rn(v.z), __float2half_rn(v.w));
}

__global__ __launch_bounds__(256) void conv_bias(const float* __restrict__ bi,
                                                 const float* __restrict__ bf_,
                                                 const float* __restrict__ bc,
                                                 const float* __restrict__ bo) {
    int idx = blockIdx.x * 256 + threadIdx.x;
    int j = idx >> 2;
    int g = idx & 3;
    g_bias[idx] = (g == 0) ? bi[j] : (g == 1) ? bf_[j] : (g == 2) ? bc[j] : bo[j];
}

// ---------------- fused GEMM + LSTM ----------------
// CTA 128(M) x 256(N'), 16 warps (4M x 4N), warp tile 32x64, BK=64.
// Single fp16 product, 4-stage cp.async, ONE __syncthreads per K-tile.
#define BK 64
#define OFF_A 0
#define OFF_B 16384
#define STAGE_BYTES 49152          // (128 + 256) rows x 128B
#define NSTAGES 4
#define BIAS_OFF    (NSTAGES * STAGE_BYTES)     // 196608
#define SMEM_TOTAL  (BIAS_OFF + 1024)           // 197632
#define NKT (K_DIM / BK)           // 32
#define NTHREADS 512
#define OUT_C_OFF ((size_t)B_ROWS * D_H)

__global__ __launch_bounds__(NTHREADS, 1) void lstm_fused(const float* __restrict__ cprev,
                                                          float* __restrict__ out) {
    extern __shared__ char smem[];
    const uint32_t sbase = smem_u32(smem);
    const int tid = threadIdx.x;
    const int lane = tid & 31;
    const int wid = tid >> 5;
    const int wm = wid & 3;            // 4 warps along M
    const int wn = wid >> 2;           // 4 warps along N
    const int aw = wm * 32;
    const int bw = wn * 64;

    const int m0 = blockIdx.y * 128;
    const int n0 = blockIdx.x * 256;   // in n' units

    float* bias_s = reinterpret_cast<float*>(smem + BIAS_OFF);
    if (tid < 256) bias_s[tid] = g_bias[n0 + tid];

    // ---- async stage loader: Ah(128r) + Bh(256r), 128B swizzled rows ----
    auto load_stage = [&](int it, int s) {
        const int kt = it * BK;
        const uint32_t st = sbase + (uint32_t)s * STAGE_BYTES;
#pragma unroll
        for (int i = 0; i < 2; i++) {                        // Ah: 128 rows x 8 chunks
            int id = i * NTHREADS + tid;
            int row = id >> 3, c = id & 7;
            uint32_t so = (uint32_t)(row * 128) + (uint32_t)((c ^ (row & 7)) << 4);
            cp_async16(st + OFF_A + so, g_Ah + (size_t)(m0 + row) * K_DIM + kt + c * 8);
        }
#pragma unroll
        for (int i = 0; i < 4; i++) {                        // Bh: 256 rows x 8 chunks
            int id = i * NTHREADS + tid;
            int row = id >> 3, c = id & 7;
            uint32_t so = (uint32_t)(row * 128) + (uint32_t)((c ^ (row & 7)) << 4);
            cp_async16(st + OFF_B + so, g_Bh + (size_t)(n0 + row) * K_DIM + kt + c * 8);
        }
        cp_commit();
    };

    float acc[2][8][4];
#pragma unroll
    for (int i = 0; i < 2; i++)
#pragma unroll
        for (int j = 0; j < 8; j++)
#pragma unroll
            for (int q = 0; q < 4; q++) acc[i][j][q] = 0.0f;

    load_stage(0, 0);
    load_stage(1, 1);
    load_stage(2, 2);

    const int aRow = aw + (lane & 15);
    const int aHi = lane >> 4;
    const int bRow = bw + (lane & 7) + ((lane >> 4) << 3);
    const int bHi = (lane >> 3) & 1;

    for (int it = 0; it < NKT; it++) {
        cp_wait<NSTAGES - 2>();        // stage `it` resident
        __syncthreads();               // all warps finished stage it-1

        if (it + NSTAGES - 1 < NKT) load_stage(it + NSTAGES - 1, (it + NSTAGES - 1) % NSTAGES);

        const uint32_t st = sbase + (uint32_t)(it % NSTAGES) * STAGE_BYTES;

#pragma unroll
        for (int ks = 0; ks < BK / 16; ks++) {
            uint32_t aH[2][4], bH[8][2];
#pragma unroll
            for (int mf = 0; mf < 2; mf++) {
                int row = aRow + mf * 16;
                int c = 2 * ks + aHi;
                uint32_t off = row * 128 + ((c ^ (row & 7)) << 4);
                ldsm4(aH[mf][0], aH[mf][1], aH[mf][2], aH[mf][3], st + OFF_A + off);
            }
#pragma unroll
            for (int nf2 = 0; nf2 < 4; nf2++) {
                int row = bRow + nf2 * 16;
                int c = 2 * ks + bHi;
                uint32_t addr = st + OFF_B + row * 128 + ((c ^ (row & 7)) << 4);
                ldsm4(bH[2 * nf2][0], bH[2 * nf2][1], bH[2 * nf2 + 1][0], bH[2 * nf2 + 1][1], addr);
            }
#pragma unroll
            for (int mf = 0; mf < 2; mf++)
#pragma unroll
                for (int nf = 0; nf < 8; nf++)
                    mma16816(acc[mf][nf][0], acc[mf][nf][1], acc[mf][nf][2], acc[mf][nf][3],
                             aH[mf][0], aH[mf][1], aH[mf][2], aH[mf][3], bH[nf][0], bH[nf][1]);
        }
    }
    __syncthreads();

    // ---- fused epilogue: stage acc to smem (bank-swizzled), then gates ----
    float* zs = reinterpret_cast<float*>(smem);      // 128 x 256 fp32 = 128KB
#pragma unroll
    for (int mf = 0; mf < 2; mf++) {
#pragma unroll
        for (int nf = 0; nf < 8; nf++) {
            int r0 = aw + mf * 16 + (lane >> 2);
            int col = bw + nf * 8 + 2 * (lane & 3);
            int c0 = col ^ ((r0 & 7) << 3);
            int c1 = col ^ (((r0 + 8) & 7) << 3);
            *reinterpret_cast<float2*>(&zs[(size_t)r0 * 256 + c0]) =
                make_float2(acc[mf][nf][0], acc[mf][nf][1]);
            *reinterpret_cast<float2*>(&zs[(size_t)(r0 + 8) * 256 + c1]) =
                make_float2(acc[mf][nf][2], acc[mf][nf][3]);
        }
    }
    __syncthreads();

    const int jbase = n0 >> 2;                       // 64 hidden units per CTA
#pragma unroll 4
    for (int r = 0; r < 16; r++) {
        int idx = r * NTHREADS + tid;                // [0, 8192) quadruples
        int ml = idx >> 6;
        int q = idx & 63;
        int cc = (4 * q) ^ ((ml & 7) << 3);
        float4 z4 = *reinterpret_cast<const float4*>(&zs[(size_t)ml * 256 + cc]);
        float zi = z4.x + bias_s[4 * q + 0];
        float zf = z4.y + bias_s[4 * q + 1];
        float zc = z4.z + bias_s[4 * q + 2];
        float zo = z4.w + bias_s[4 * q + 3];
        int m = m0 + ml;
        int j = jbase + q;
        float cp = cprev[(size_t)m * D_H + j];
        float ig = 1.0f / (1.0f + expf(-zi));
        float fg = 1.0f / (1.0f + expf(-zf));
        float cg = tanhf(zc);
        float og = 1.0f / (1.0f + expf(-zo));
        float cn = fg * cp + ig * cg;
        float hn = og * tanhf(cn);
        out[(size_t)m * D_H + j] = hn;
        out[OUT_C_OFF + (size_t)m * D_H + j] = cn;
    }
}

// ---------------- launch ----------------
extern "C" void kernel_launch(void* const* d_in, const int* in_sizes, int n_in,
                              void* d_out, int out_size)
{
    const float* x  = (const float*)d_in[0];
    const float* h  = (const float*)d_in[1];
    const float* c  = (const float*)d_in[2];
    const float* Wi = (const float*)d_in[3];
    const float* bi = (const float*)d_in[4];
    const float* Wf = (const float*)d_in[5];
    const float* bf = (const float*)d_in[6];
    const float* Wc = (const float*)d_in[7];
    const float* bc = (const float*)d_in[8];
    const float* Wo = (const float*)d_in[9];
    const float* bo = (const float*)d_in[10];
    float* out = (float*)d_out;

    static bool attr_set = false;
    if (!attr_set) {
        cudaFuncSetAttribute(lstm_fused, cudaFuncAttributeMaxDynamicSharedMemorySize, SMEM_TOTAL);
        attr_set = true;
    }

    conv_A<<<(B_ROWS * K_DIM / 4) / 256, 256>>>(x, h);
    conv_B<<<(N_DIM * K_DIM / 4) / 256, 256>>>(Wi, Wf, Wc, Wo);
    conv_bias<<<N_DIM / 256, 256>>>(bi, bf, bc, bo);

    dim3 grid(N_DIM / 256, B_ROWS / 128);   // 16 x 32 = 512 CTAs
    lstm_fused<<<grid, NTHREADS, SMEM_TOTAL>>>(c, out);
}

// round 8
// speedup vs baseline: 9.0426x; 1.1817x over previous
#include <cuda_runtime.h>
#include <cuda_fp16.h>
#include <math.h>
#include <stdint.h>

#define B_ROWS 4096
#define D_H    1024
#define K_DIM  2048
#define N_DIM  4096

// ---------------- static device scratch ----------------
__device__ __align__(128) __half g_Ah[(size_t)B_ROWS * K_DIM];
__device__ __align__(128) __half g_Bh[(size_t)N_DIM * K_DIM];   // interleaved rows n' = 4j+g
__device__ __align__(128) float  g_bias[N_DIM];                 // interleaved

// ---------------- helpers ----------------
__device__ __forceinline__ uint32_t smem_u32(const void* p) {
    uint32_t a;
    asm("{ .reg .u64 t; cvta.to.shared.u64 t, %1; cvt.u32.u64 %0, t; }" : "=r"(a) : "l"(p));
    return a;
}
__device__ __forceinline__ void cp_async16(uint32_t dst, const void* src) {
    asm volatile("cp.async.cg.shared.global [%0], [%1], 16;" :: "r"(dst), "l"(src) : "memory");
}
__device__ __forceinline__ void cp_commit() {
    asm volatile("cp.async.commit_group;" ::: "memory");
}
template <int N>
__device__ __forceinline__ void cp_wait() {
    asm volatile("cp.async.wait_group %0;" :: "n"(N) : "memory");
}
__device__ __forceinline__ void ldsm4(uint32_t& r0, uint32_t& r1, uint32_t& r2, uint32_t& r3,
                                      uint32_t addr) {
    asm volatile("ldmatrix.sync.aligned.m8n8.x4.shared.b16 {%0,%1,%2,%3}, [%4];"
                 : "=r"(r0), "=r"(r1), "=r"(r2), "=r"(r3) : "r"(addr));
}
__device__ __forceinline__ void mma16816(float& d0, float& d1, float& d2, float& d3,
                                         uint32_t a0, uint32_t a1, uint32_t a2, uint32_t a3,
                                         uint32_t b0, uint32_t b1) {
    asm volatile(
        "mma.sync.aligned.m16n8k16.row.col.f32.f16.f16.f32 "
        "{%0,%1,%2,%3}, {%4,%5,%6,%7}, {%8,%9}, {%0,%1,%2,%3};"
        : "+f"(d0), "+f"(d1), "+f"(d2), "+f"(d3)
        : "r"(a0), "r"(a1), "r"(a2), "r"(a3), "r"(b0), "r"(b1));
}

// ---------------- conversion kernels ----------------
__global__ __launch_bounds__(256) void conv_A(const float* __restrict__ x,
                                              const float* __restrict__ h) {
    size_t e = ((size_t)blockIdx.x * 256 + threadIdx.x) * 4;
    int m = (int)(e >> 11);
    int k = (int)(e & 2047);
    const float* src = (k < 1024) ? &x[(size_t)m * 1024 + k] : &h[(size_t)m * 1024 + (k - 1024)];
    float4 v = *reinterpret_cast<const float4*>(src);
    *reinterpret_cast<__half2*>(&g_Ah[e])     = __halves2half2(__float2half_rn(v.x), __float2half_rn(v.y));
    *reinterpret_cast<__half2*>(&g_Ah[e + 2]) = __halves2half2(__float2half_rn(v.z), __float2half_rn(v.w));
}

__global__ __launch_bounds__(256) void conv_B(const float* __restrict__ Wi,
                                              const float* __restrict__ Wf,
                                              const float* __restrict__ Wc,
                                              const float* __restrict__ Wo) {
    size_t e = ((size_t)blockIdx.x * 256 + threadIdx.x) * 4;
    int np = (int)(e >> 11);     // n' = 4*j + gate (interleaved)
    int k = (int)(e & 2047);
    int j = np >> 2;
    int g = np & 3;
    const float* W = (g == 0) ? Wi : (g == 1) ? Wf : (g == 2) ? Wc : Wo;
    float4 v = *reinterpret_cast<const float4*>(&W[(size_t)j * K_DIM + k]);
    *reinterpret_cast<__half2*>(&g_Bh[e])     = __halves2half2(__float2half_rn(v.x), __float2half_rn(v.y));
    *reinterpret_cast<__half2*>(&g_Bh[e + 2]) = __halves2half2(__float2half_rn(v.z), __float2half_rn(v.w));
}

__global__ __launch_bounds__(256) void conv_bias(const float* __restrict__ bi,
                                                 const float* __restrict__ bf_,
                                                 const float* __restrict__ bc,
                                                 const float* __restrict__ bo) {
    int idx = blockIdx.x * 256 + threadIdx.x;
    int j = idx >> 2;
    int g = idx & 3;
    g_bias[idx] = (g == 0) ? bi[j] : (g == 1) ? bf_[j] : (g == 2) ? bc[j] : bo[j];
}

// ---------------- fused GEMM + LSTM ----------------
// CTA 128(M) x 128(N'), 8 warps (4M x 2N), warp tile 32x64, BK=64, 3-stage.
// TWO CTAs per SM (launch_bounds(256,2)) for barrier-independent overlap.
#define BK 64
#define OFF_A 0
#define OFF_B 16384
#define STAGE_BYTES 32768          // (128 + 128) rows x 128B
#define NSTAGES 3
#define BIAS_OFF    (NSTAGES * STAGE_BYTES)     // 98304
#define SMEM_TOTAL  (BIAS_OFF + 512)            // 98816
#define NKT (K_DIM / BK)           // 32
#define NTHREADS 256
#define OUT_C_OFF ((size_t)B_ROWS * D_H)

__global__ __launch_bounds__(NTHREADS, 2) void lstm_fused(const float* __restrict__ cprev,
                                                          float* __restrict__ out) {
    extern __shared__ char smem[];
    const uint32_t sbase = smem_u32(smem);
    const int tid = threadIdx.x;
    const int lane = tid & 31;
    const int wid = tid >> 5;
    const int wm = wid & 3;            // 4 warps along M
    const int wn = wid >> 2;           // 2 warps along N
    const int aw = wm * 32;
    const int bw = wn * 64;

    const int m0 = blockIdx.y * 128;
    const int n0 = blockIdx.x * 128;   // in n' units

    float* bias_s = reinterpret_cast<float*>(smem + BIAS_OFF);
    if (tid < 128) bias_s[tid] = g_bias[n0 + tid];

    // ---- async stage loader: Ah(128r) + Bh(128r), 128B swizzled rows ----
    auto load_stage = [&](int it, int s) {
        const int kt = it * BK;
        const uint32_t st = sbase + (uint32_t)s * STAGE_BYTES;
#pragma unroll
        for (int i = 0; i < 4; i++) {                        // Ah: 128 rows x 8 chunks
            int id = i * NTHREADS + tid;
            int row = id >> 3, c = id & 7;
            uint32_t so = (uint32_t)(row * 128) + (uint32_t)((c ^ (row & 7)) << 4);
            cp_async16(st + OFF_A + so, g_Ah + (size_t)(m0 + row) * K_DIM + kt + c * 8);
        }
#pragma unroll
        for (int i = 0; i < 4; i++) {                        // Bh: 128 rows x 8 chunks
            int id = i * NTHREADS + tid;
            int row = id >> 3, c = id & 7;
            uint32_t so = (uint32_t)(row * 128) + (uint32_t)((c ^ (row & 7)) << 4);
            cp_async16(st + OFF_B + so, g_Bh + (size_t)(n0 + row) * K_DIM + kt + c * 8);
        }
        cp_commit();
    };

    float acc[2][8][4];
#pragma unroll
    for (int i = 0; i < 2; i++)
#pragma unroll
        for (int j = 0; j < 8; j++)
#pragma unroll
            for (int q = 0; q < 4; q++) acc[i][j][q] = 0.0f;

    load_stage(0, 0);
    load_stage(1, 1);

    const int aRow = aw + (lane & 15);
    const int aHi = lane >> 4;
    const int bRow = bw + (lane & 7) + ((lane >> 4) << 3);
    const int bHi = (lane >> 3) & 1;

    for (int it = 0; it < NKT; it++) {
        cp_wait<NSTAGES - 2>();        // stage `it` resident
        __syncthreads();               // all warps finished stage it-1

        if (it + NSTAGES - 1 < NKT) load_stage(it + NSTAGES - 1, (it + NSTAGES - 1) % NSTAGES);

        const uint32_t st = sbase + (uint32_t)(it % NSTAGES) * STAGE_BYTES;

#pragma unroll
        for (int ks = 0; ks < BK / 16; ks++) {
            uint32_t aH[2][4], bH[8][2];
#pragma unroll
            for (int mf = 0; mf < 2; mf++) {
                int row = aRow + mf * 16;
                int c = 2 * ks + aHi;
                uint32_t off = row * 128 + ((c ^ (row & 7)) << 4);
                ldsm4(aH[mf][0], aH[mf][1], aH[mf][2], aH[mf][3], st + OFF_A + off);
            }
#pragma unroll
            for (int nf2 = 0; nf2 < 4; nf2++) {
                int row = bRow + nf2 * 16;
                int c = 2 * ks + bHi;
                uint32_t addr = st + OFF_B + row * 128 + ((c ^ (row & 7)) << 4);
                ldsm4(bH[2 * nf2][0], bH[2 * nf2][1], bH[2 * nf2 + 1][0], bH[2 * nf2 + 1][1], addr);
            }
#pragma unroll
            for (int mf = 0; mf < 2; mf++)
#pragma unroll
                for (int nf = 0; nf < 8; nf++)
                    mma16816(acc[mf][nf][0], acc[mf][nf][1], acc[mf][nf][2], acc[mf][nf][3],
                             aH[mf][0], aH[mf][1], aH[mf][2], aH[mf][3], bH[nf][0], bH[nf][1]);
        }
    }
    __syncthreads();

    // ---- fused epilogue: stage acc to smem (bank-swizzled 128-col rows) ----
    float* zs = reinterpret_cast<float*>(smem);      // 128 x 128 fp32 = 64KB
#pragma unroll
    for (int mf = 0; mf < 2; mf++) {
#pragma unroll
        for (int nf = 0; nf < 8; nf++) {
            int r0 = aw + mf * 16 + (lane >> 2);
            int col = bw + nf * 8 + 2 * (lane & 3);
            int c0 = col ^ ((r0 & 7) << 3);
            int c1 = col ^ (((r0 + 8) & 7) << 3);
            *reinterpret_cast<float2*>(&zs[(size_t)r0 * 128 + c0]) =
                make_float2(acc[mf][nf][0], acc[mf][nf][1]);
            *reinterpret_cast<float2*>(&zs[(size_t)(r0 + 8) * 128 + c1]) =
                make_float2(acc[mf][nf][2], acc[mf][nf][3]);
        }
    }
    __syncthreads();

    const int jbase = n0 >> 2;                       // 32 hidden units per CTA
#pragma unroll 4
    for (int r = 0; r < 16; r++) {
        int idx = r * NTHREADS + tid;                // [0, 4096) quadruples
        int ml = idx >> 5;
        int q = idx & 31;
        int cc = (4 * q) ^ ((ml & 7) << 3);
        float4 z4 = *reinterpret_cast<const float4*>(&zs[(size_t)ml * 128 + cc]);
        float zi = z4.x + bias_s[4 * q + 0];
        float zf = z4.y + bias_s[4 * q + 1];
        float zc = z4.z + bias_s[4 * q + 2];
        float zo = z4.w + bias_s[4 * q + 3];
        int m = m0 + ml;
        int j = jbase + q;
        float cp = cprev[(size_t)m * D_H + j];
        float ig = 1.0f / (1.0f + expf(-zi));
        float fg = 1.0f / (1.0f + expf(-zf));
        float cg = tanhf(zc);
        float og = 1.0f / (1.0f + expf(-zo));
        float cn = fg * cp + ig * cg;
        float hn = og * tanhf(cn);
        out[(size_t)m * D_H + j] = hn;
        out[OUT_C_OFF + (size_t)m * D_H + j] = cn;
    }
}

// ---------------- launch ----------------
extern "C" void kernel_launch(void* const* d_in, const int* in_sizes, int n_in,
                              void* d_out, int out_size)
{
    const float* x  = (const float*)d_in[0];
    const float* h  = (const float*)d_in[1];
    const float* c  = (const float*)d_in[2];
    const float* Wi = (const float*)d_in[3];
    const float* bi = (const float*)d_in[4];
    const float* Wf = (const float*)d_in[5];
    const float* bf = (const float*)d_in[6];
    const float* Wc = (const float*)d_in[7];
    const float* bc = (const float*)d_in[8];
    const float* Wo = (const float*)d_in[9];
    const float* bo = (const float*)d_in[10];
    float* out = (float*)d_out;

    static bool attr_set = false;
    if (!attr_set) {
        cudaFuncSetAttribute(lstm_fused, cudaFuncAttributeMaxDynamicSharedMemorySize, SMEM_TOTAL);
        attr_set = true;
    }

    conv_A<<<(B_ROWS * K_DIM / 4) / 256, 256>>>(x, h);
    conv_B<<<(N_DIM * K_DIM / 4) / 256, 256>>>(Wi, Wf, Wc, Wo);
    conv_bias<<<N_DIM / 256, 256>>>(bi, bf, bc, bo);

    dim3 grid(N_DIM / 128, B_ROWS / 128);   // 32 x 32 = 1024 CTAs
    lstm_fused<<<grid, NTHREADS, SMEM_TOTAL>>>(c, out);
}